// round 6
// baseline (speedup 1.0000x reference)
#include <cuda_runtime.h>
#include <cstddef>

#define FFT_N 8192
#define NT    1024
#define CH    64

// XOR swizzle on float2 index: conflict-free (<=2-way worst case) for all
// access patterns used here.
#define SWZ(a) ((a) ^ (((a) >> 4) & 15))

__device__ __forceinline__ float2 cmul(float2 a, float2 b) {
    return make_float2(fmaf(a.x, b.x, -a.y * b.y), fmaf(a.x, b.y, a.y * b.x));
}
__device__ __forceinline__ float2 cadd(float2 a, float2 b) { return make_float2(a.x + b.x, a.y + b.y); }
__device__ __forceinline__ float2 csub(float2 a, float2 b) { return make_float2(a.x - b.x, a.y - b.y); }

template<int DIR>
__device__ __forceinline__ void dft4(float2& a, float2& b, float2& c, float2& d) {
    float2 t0 = cadd(a, c), t1 = csub(a, c);
    float2 t2 = cadd(b, d), t3 = csub(b, d);
    a = cadd(t0, t2);
    c = csub(t0, t2);
    if (DIR > 0) {
        b = make_float2(t1.x + t3.y, t1.y - t3.x);
        d = make_float2(t1.x - t3.y, t1.y + t3.x);
    } else {
        b = make_float2(t1.x - t3.y, t1.y + t3.x);
        d = make_float2(t1.x + t3.y, t1.y - t3.x);
    }
}

// In-place DFT8, natural-order outputs.
template<int DIR>
__device__ __forceinline__ void dft8(float2 v[8]) {
    dft4<DIR>(v[0], v[2], v[4], v[6]);
    dft4<DIR>(v[1], v[3], v[5], v[7]);
    const float C2 = 0.70710678118654752f;
    const float s  = (DIR > 0) ? 1.0f : -1.0f;
    v[3] = cmul(v[3], make_float2( C2, -s * C2));
    v[5] = cmul(v[5], make_float2(0.f, -s      ));
    v[7] = cmul(v[7], make_float2(-C2, -s * C2));
    float2 y[8];
    #pragma unroll
    for (int k2 = 0; k2 < 4; k2++) {
        y[k2]     = cadd(v[2 * k2], v[2 * k2 + 1]);
        y[k2 + 4] = csub(v[2 * k2], v[2 * k2 + 1]);
    }
    #pragma unroll
    for (int o = 0; o < 8; o++) v[o] = y[o];
}

template<int S, int DIR>
__device__ __forceinline__ void stage_read(const float2* __restrict__ buf, int j,
                                           float2 w1, float2 v[8]) {
    #pragma unroll
    for (int r = 0; r < 8; r++)
        v[r] = buf[SWZ(j + r * (FFT_N / 8))];
    if (S > 1) {
        float2 w = w1;
        #pragma unroll
        for (int r = 1; r < 8; r++) {
            v[r] = cmul(v[r], w);
            if (r < 7) w = cmul(w, w1);
        }
    }
    dft8<DIR>(v);
}

template<int S>
__device__ __forceinline__ void stage_write(float2* __restrict__ buf, int j,
                                            const float2 v[8]) {
    const int jq   = j & (S - 1);
    const int base = jq + (j / S) * (S * 8);
    #pragma unroll
    for (int o = 0; o < 8; o++)
        buf[SWZ(base + S * o)] = v[o];
}

// One in-place radix-8 stage applied to both buffers (guarded per pair).
template<int S, int DIR>
__device__ __forceinline__ void stage_pair(float2* b0, float2* b1, int j,
                                           bool p0, bool p1) {
    float2 w1 = make_float2(1.f, 0.f);
    if (S > 1) {
        float ss, cc;
        sincospif((DIR > 0 ? -2.0f : 2.0f) * (float)(j & (S - 1)) / (8.0f * (float)S), &ss, &cc);
        w1 = make_float2(cc, ss);
    }
    float2 v[8];
    if (p0) stage_read<S, DIR>(b0, j, w1, v);
    __syncthreads();
    if (p0) stage_write<S>(b0, j, v);
    if (p1) stage_read<S, DIR>(b1, j, w1, v);
    __syncthreads();
    if (p1) stage_write<S>(b1, j, v);
    __syncthreads();
}

// Hermitian rebuild for one (ka, kb=(N-ka)%N) pair of one buffer, given the
// forward-FFT values Za=Z[ka], Zb=Z[kb] and the two channels' phases at
// (ka,kb): phA=(phi_A(ka), phi_A(kb)), phB likewise. Writes W in place.
__device__ __forceinline__ void rebuild(float2* __restrict__ buf, int ka, int kb,
                                        float2 Za, float2 Zb,
                                        float2 phA, float2 phB) {
    const float TWO_PI = 6.283185307179586476925f;
    const float scale  = 0.25f / (float)FFT_N;
    float ax = Za.x + Zb.x, ay = Za.y - Zb.y;
    float bx = Za.y + Zb.y, by = Zb.x - Za.x;
    float ampA = sqrtf(fmaf(ax, ax, ay * ay)) * scale;
    float ampB = sqrtf(fmaf(bx, bx, by * by)) * scale;
    float sA1, cA1, sA2, cA2, sB1, cB1, sB2, cB2;
    __sincosf(TWO_PI * phA.x, &sA1, &cA1);
    __sincosf(TWO_PI * phA.y, &sA2, &cA2);
    __sincosf(TWO_PI * phB.x, &sB1, &cB1);
    __sincosf(TWO_PI * phB.y, &sB2, &cB2);
    float h1x = ampA * (cA1 + cA2), h1y = ampA * (sA1 - sA2);
    float h2x = ampB * (cB1 + cB2), h2y = ampB * (sB1 - sB2);
    buf[SWZ(ka)] = make_float2(h1x - h2y, h1y + h2x);
    buf[SWZ(kb)] = make_float2(h1x + h2y, h2x - h1y);
}

// Fused forward-radix-2 + Hermitian rebuild for index-group
// {k, 4096-k, 4096+k, 8192-k}. Each group is closed under both the final
// radix-2 butterfly and Hermitian pairing -> thread-local, no barriers.
// LANE=0 uses float4 lanes (x,y), LANE=1 uses (z,w).
template<int LANE>
__device__ __forceinline__ void group_rebuild(float2* __restrict__ buf,
                                              const float4* __restrict__ p4, int k) {
    if (k == 0) {
        float2 bk = buf[SWZ(0)], bh = buf[SWZ(4096)];
        float2 Z0 = cadd(bk, bh), Z4 = csub(bk, bh);
        float4 q0 = p4[0];
        float4 q4 = p4[(size_t)4096 * 16];
        if (LANE == 0) {
            rebuild(buf, 0,    0,    Z0, Z0, make_float2(q0.x, q0.x), make_float2(q0.y, q0.y));
            rebuild(buf, 4096, 4096, Z4, Z4, make_float2(q4.x, q4.x), make_float2(q4.y, q4.y));
        } else {
            rebuild(buf, 0,    0,    Z0, Z0, make_float2(q0.z, q0.z), make_float2(q0.w, q0.w));
            rebuild(buf, 4096, 4096, Z4, Z4, make_float2(q4.z, q4.z), make_float2(q4.w, q4.w));
        }
        return;
    }
    const int k2 = 4096 - k, k3 = 4096 + k, k4 = 8192 - k;
    float ss, cc;
    sincospif(-(float)k / 4096.0f, &ss, &cc);
    float2 w1 = make_float2(cc, ss);
    {
        float2 u0 = buf[SWZ(k)], u1 = cmul(buf[SWZ(k3)], w1);
        float2 Zk  = cadd(u0, u1);
        float2 Zk3 = csub(u0, u1);
        if (k == 2048) {
            // Group degenerates to {2048, 6144}: one pair.
            float4 qa = p4[(size_t)k  * 16];
            float4 qb = p4[(size_t)k3 * 16];
            if (LANE == 0)
                rebuild(buf, k, k3, Zk, Zk3, make_float2(qa.x, qb.x), make_float2(qa.y, qb.y));
            else
                rebuild(buf, k, k3, Zk, Zk3, make_float2(qa.z, qb.z), make_float2(qa.w, qb.w));
            return;
        }
        // w for j=k2: e^{-i*pi*(4096-k)/4096} = -conj(w1)
        float2 w2 = make_float2(-w1.x, w1.y);
        float2 v0 = buf[SWZ(k2)], v1 = cmul(buf[SWZ(k4)], w2);
        float2 Zk2 = cadd(v0, v1);
        float2 Zk4 = csub(v0, v1);
        {
            float4 qa = p4[(size_t)k  * 16];
            float4 qb = p4[(size_t)k4 * 16];
            if (LANE == 0)
                rebuild(buf, k, k4, Zk, Zk4, make_float2(qa.x, qb.x), make_float2(qa.y, qb.y));
            else
                rebuild(buf, k, k4, Zk, Zk4, make_float2(qa.z, qb.z), make_float2(qa.w, qb.w));
        }
        {
            float4 qa = p4[(size_t)k2 * 16];
            float4 qb = p4[(size_t)k3 * 16];
            if (LANE == 0)
                rebuild(buf, k2, k3, Zk2, Zk3, make_float2(qa.x, qb.x), make_float2(qa.y, qb.y));
            else
                rebuild(buf, k2, k3, Zk2, Zk3, make_float2(qa.z, qb.z), make_float2(qa.w, qb.w));
        }
    }
}

__global__ __launch_bounds__(NT, 1)
void surrogate_kernel(const float* __restrict__ wave,
                      const float* __restrict__ phases,
                      const float* __restrict__ mask,
                      float* __restrict__ out) {
    const int blk = blockIdx.x;
    const int b   = blk >> 4;
    const int c0  = (blk & 15) * 4;
    const int tid = threadIdx.x;

    const bool s0 = mask[b * CH + c0]     < 0.5f;
    const bool s1 = mask[b * CH + c0 + 1] < 0.5f;
    const bool s2 = mask[b * CH + c0 + 2] < 0.5f;
    const bool s3 = mask[b * CH + c0 + 3] < 0.5f;
    const bool p0 = s0 | s1;
    const bool p1 = s2 | s3;
    const bool m0 = p0 && !(s0 && s1);   // pair0 mixed: one kept lane -> stash
    const bool m1 = p1 && !(s2 && s3);

    const float4* w4 = (const float4*)(wave   + (size_t)b * FFT_N * CH + c0);
    const float4* p4 = (const float4*)(phases + (size_t)b * FFT_N * CH + c0);
    float4*       o4 = (float4*)      (out    + (size_t)b * FFT_N * CH + c0);

    if (!p0 && !p1) {
        #pragma unroll 4
        for (int t = tid; t < FFT_N; t += NT)
            o4[(size_t)t * 16] = w4[(size_t)t * 16];
        return;
    }

    extern __shared__ float2 sm[];
    float2* b0    = sm;                        // pair 0
    float2* b1    = sm + FFT_N;                // pair 1
    float*  stash = (float*)(sm + 2 * FFT_N);  // kept-lane originals, 2 x 8192 floats

    // ---- Load: one float4 per sample -> both buffers (+stash kept lanes) --
    #pragma unroll
    for (int i = 0; i < FFT_N / NT; i++) {
        int t = tid + i * NT;
        float4 g = w4[(size_t)t * 16];
        b0[SWZ(t)] = make_float2(g.x, g.y);
        b1[SWZ(t)] = make_float2(g.z, g.w);
        if (m0) stash[t]         = s0 ? g.y : g.x;
        if (m1) stash[FFT_N + t] = s2 ? g.w : g.z;
    }
    __syncthreads();

    // ---- Forward FFT: radix-8 x4 in place ----------------------------------
    stage_pair<1,   1>(b0, b1, tid, p0, p1);
    stage_pair<8,   1>(b0, b1, tid, p0, p1);
    stage_pair<64,  1>(b0, b1, tid, p0, p1);
    stage_pair<512, 1>(b0, b1, tid, p0, p1);

    // ---- Fused final radix-2 + spectrum rebuild (thread-local groups) ------
    for (int k = tid; k <= 2048; k += NT) {
        if (p0) group_rebuild<0>(b0, p4, k);
        if (p1) group_rebuild<1>(b1, p4, k);
    }
    __syncthreads();

    // ---- Inverse FFT --------------------------------------------------------
    stage_pair<1,   -1>(b0, b1, tid, p0, p1);
    stage_pair<8,   -1>(b0, b1, tid, p0, p1);
    stage_pair<64,  -1>(b0, b1, tid, p0, p1);
    stage_pair<512, -1>(b0, b1, tid, p0, p1);

    // ---- Final inverse radix-2 + select + float4 store (no gmem reload) ----
    #pragma unroll
    for (int i = 0; i < FFT_N / 2 / NT; i++) {
        int j = tid + i * NT;
        float ss, cc;
        sincospif((float)j / 4096.0f, &ss, &cc);
        float2 w = make_float2(cc, ss);
        float2 y0, y1, z0, z1;
        if (p0) {
            float2 u0 = b0[SWZ(j)], u1 = cmul(b0[SWZ(j + 4096)], w);
            y0 = cadd(u0, u1);  y1 = csub(u0, u1);
            if (m0) {
                float oa = stash[j], ob = stash[j + 4096];
                if (s0) { y0.y = oa; y1.y = ob; }   // ch1 kept
                else    { y0.x = oa; y1.x = ob; }   // ch0 kept
            }
        } else {   // pair fully kept: buffer still holds originals
            y0 = b0[SWZ(j)];  y1 = b0[SWZ(j + 4096)];
        }
        if (p1) {
            float2 u0 = b1[SWZ(j)], u1 = cmul(b1[SWZ(j + 4096)], w);
            z0 = cadd(u0, u1);  z1 = csub(u0, u1);
            if (m1) {
                float oa = stash[FFT_N + j], ob = stash[FFT_N + j + 4096];
                if (s2) { z0.y = oa; z1.y = ob; }
                else    { z0.x = oa; z1.x = ob; }
            }
        } else {
            z0 = b1[SWZ(j)];  z1 = b1[SWZ(j + 4096)];
        }
        o4[(size_t)j * 16]          = make_float4(y0.x, y0.y, z0.x, z0.y);
        o4[(size_t)(j + 4096) * 16] = make_float4(y1.x, y1.y, z1.x, z1.y);
    }
}

extern "C" void kernel_launch(void* const* d_in, const int* in_sizes, int n_in,
                              void* d_out, int out_size) {
    const float* wave   = (const float*)d_in[0];
    const float* phases = (const float*)d_in[1];
    const float* maskp  = (const float*)d_in[2];
    float* out = (float*)d_out;

    const int B = in_sizes[0] / (FFT_N * CH);
    const int smem = 2 * FFT_N * (int)sizeof(float2) + 2 * FFT_N * (int)sizeof(float); // 196,608 B

    cudaFuncSetAttribute(surrogate_kernel,
                         cudaFuncAttributeMaxDynamicSharedMemorySize, smem);
    surrogate_kernel<<<B * (CH / 4), NT, smem>>>(wave, phases, maskp, out);
}